// round 14
// baseline (speedup 1.0000x reference)
#include <cuda_runtime.h>
#include <cuda_fp16.h>
#include <cstdint>

#define BB 2
#define TT 16
#define NN 256
#define MM 1152
#define HH 16
#define DD 72
#define ROWS 8192
#define ADAW 6912
#define QKVW 3456
#define MLPW 4608
#define SCALE 0.11785113019775793f

// ---------------- scratch -----------------------------------------------
__device__ float  g_x4[ROWS * MM];
__device__ __half g_lnh[ROWS * MM];
__device__ __half g_attnh[ROWS * MM];
__device__ __half g_bigh[(size_t)ROWS * MLPW];
__device__ float  g_ada[BB * ADAW];
__device__ float  g_tk[BB * TT * MM];
__device__ float  g_tv[BB * TT * MM];
__device__ float  g_sk[BB * TT * MM];
__device__ float  g_sv[BB * TT * MM];
__device__ float  g_ropec[TT * (DD / 2)];
__device__ float  g_ropes[TT * (DD / 2)];
// half weights
__device__ __half g_wh_tqkv[(size_t)QKVW * MM];   // [N][K]
__device__ __half g_wh_toutrm[(size_t)MM * MM];   // t_out row-major (convert only)
__device__ __half g_wh_tfc[(size_t)MM * MM];      // t_fc^T [N][K]
__device__ __half g_wh_comb[(size_t)MM * MM];     // (t_out@t_fc)^T [N][K]
__device__ __half g_wh_sqkv[(size_t)QKVW * MM];
__device__ __half g_wh_sout[(size_t)MM * MM];
__device__ __half g_wh_w1[(size_t)MLPW * MM];
__device__ __half g_wh_w2[(size_t)MM * MLPW];

// ---------------- helpers -------------------------------------------------
__device__ __forceinline__ uint32_t s2u(const void* p) {
    uint32_t a;
    asm("{ .reg .u64 t; cvta.to.shared.u64 t, %1; cvt.u32.u64 %0, t; }"
        : "=r"(a) : "l"(p));
    return a;
}
__device__ __forceinline__ void cpa16(void* s, const void* g) {
    asm volatile("cp.async.cg.shared.global [%0], [%1], 16;" :: "r"(s2u(s)), "l"(g));
}
__device__ __forceinline__ void ldsm4(uint32_t* r, const void* p) {
    asm volatile("ldmatrix.sync.aligned.m8n8.x4.shared.b16 {%0,%1,%2,%3}, [%4];"
        : "=r"(r[0]), "=r"(r[1]), "=r"(r[2]), "=r"(r[3]) : "r"(s2u(p)));
}
__device__ __forceinline__ void mma16816(float* d, const uint32_t* a, const uint32_t* b) {
    asm volatile(
        "mma.sync.aligned.m16n8k16.row.col.f32.f16.f16.f32 "
        "{%0,%1,%2,%3},{%4,%5,%6,%7},{%8,%9},{%0,%1,%2,%3};"
        : "+f"(d[0]), "+f"(d[1]), "+f"(d[2]), "+f"(d[3])
        : "r"(a[0]), "r"(a[1]), "r"(a[2]), "r"(a[3]), "r"(b[0]), "r"(b[1]));
}

// ---------------- weight transpose+convert [K,N]f32 -> [N,K]h ------------
__global__ __launch_bounds__(256) void convw_kernel(
    const float* __restrict__ S, __half* __restrict__ D, int K, int N)
{
    __shared__ float t[32][33];
    int x = blockIdx.x * 32 + threadIdx.x;
    int y0 = blockIdx.y * 32;
#pragma unroll
    for (int j = threadIdx.y; j < 32; j += 8)
        t[j][threadIdx.x] = S[(size_t)(y0 + j) * N + x];
    __syncthreads();
    int x2 = y0 + threadIdx.x;
    int y2 = blockIdx.x * 32;
#pragma unroll
    for (int j = threadIdx.y; j < 32; j += 8)
        D[(size_t)(y2 + j) * K + x2] = __float2half(t[threadIdx.x][j]);
}

// ---------------- plain convert f32 -> half (same layout) ------------------
__global__ __launch_bounds__(256) void convh_kernel(
    const float* __restrict__ S, __half* __restrict__ D, int total)
{
    int i = blockIdx.x * 256 + threadIdx.x;
    if (i < total) D[i] = __float2half(S[i]);
}

// ---------------- fp16 mma GEMM, templated M-tile --------------------------
// MT=256: warp tile 64x64, 1 CTA/SM.  MT=128: warp tile 32x64, 2 CTAs/SM.
// 4-stage cp.async ring (wait -> barrier -> prefetch -> compute), ldmatrix.
// smem row stride 40 halves (80B): ldsm rows partition all 32 banks.
#define HSTR 40
#define NSTG 4
template<int MT>
__global__ __launch_bounds__(256, MT == 128 ? 2 : 1) void tc_gemm_kernel(
    const __half* __restrict__ A, const __half* __restrict__ W,
    const float* __restrict__ bias, const float* __restrict__ addsrc,
    const float* __restrict__ gate,
    float* __restrict__ Cf, __half* __restrict__ Ch,
    int K, int Nc, int act, int permute)
{
    constexpr int TILE_A = MT * HSTR;        // halves
    constexpr int TILE_B = 128 * HSTR;
    constexpr int STAGE = TILE_A + TILE_B;
    constexpr int MTC = MT / 64;             // m16 tiles per warp (2 or 4)
    constexpr int ASEG = MT / 64;            // A cp.async segs per thread... (MT*4/256)
    extern __shared__ __half smem[];
    int tid = threadIdx.x, lane = tid & 31, wid = tid >> 5;
    int wm = wid & 3, wn = wid >> 2;
    int qrow = lane >> 2, qk = lane & 3;
    int blockCol = blockIdx.x * 128, blockRow = blockIdx.y * MT;
    int nc = K >> 5;

    float acc[MTC][8][4];
#pragma unroll
    for (int mt = 0; mt < MTC; mt++)
#pragma unroll
        for (int nt = 0; nt < 8; nt++)
#pragma unroll
            for (int r = 0; r < 4; r++) acc[mt][nt][r] = 0.f;

    const __half* Ab = A + (size_t)blockRow * K;
    const __half* Bb = W + (size_t)blockCol * K;

    // ldmatrix addresses (half offsets within tile)
    int amrow = wm * (MT / 4) + (lane & 15);
    int akoff = (lane >> 4) << 3;
    int bnrow = wn * 64 + (lane & 7) + ((lane >> 4) << 3);
    int bkoff = ((lane >> 3) & 1) << 3;

#define PREFETCH(chunk, stg_) do {                                              \
    __half* As_ = smem + (stg_) * STAGE;                                         \
    __half* Bs_ = As_ + TILE_A;                                                  \
    int k0 = (chunk) << 5;                                                       \
    _Pragma("unroll")                                                            \
    for (int j = 0; j < ASEG; j++) {                                             \
        int seg = tid + j * 256;                                                 \
        int ar = seg >> 2, as = seg & 3;                                         \
        cpa16(As_ + ar * HSTR + as * 8, Ab + (size_t)ar * K + k0 + as * 8);      \
    }                                                                            \
    _Pragma("unroll")                                                            \
    for (int j = 0; j < 2; j++) {                                                \
        int seg = tid + j * 256;                                                 \
        int br = seg >> 2, bs = seg & 3;                                         \
        cpa16(Bs_ + br * HSTR + bs * 8, Bb + (size_t)br * K + k0 + bs * 8);      \
    }                                                                            \
    asm volatile("cp.async.commit_group;" ::: "memory");                         \
} while (0)

    PREFETCH(0, 0);
    if (nc > 1) PREFETCH(1, 1);
    if (nc > 2) PREFETCH(2, 2);

    int stg = 0;
#pragma unroll 1
    for (int i = 0; i < nc; i++) {
        int rem = nc - 1 - i;
        if (rem >= 2)      asm volatile("cp.async.wait_group 2;" ::: "memory");
        else if (rem == 1) asm volatile("cp.async.wait_group 1;" ::: "memory");
        else               asm volatile("cp.async.wait_group 0;" ::: "memory");
        __syncthreads();
        if (i + 3 < nc)
            PREFETCH(i + 3, (stg == 0) ? (NSTG - 1) : stg - 1);
        const __half* As = smem + stg * STAGE;
        const __half* Bs = As + TILE_A;
#pragma unroll
        for (int kk = 0; kk < 2; kk++) {
            int kb = kk * 16;
            uint32_t a[MTC][4], b[4][4];
#pragma unroll
            for (int mt = 0; mt < MTC; mt++)
                ldsm4(a[mt], As + (amrow + mt * 16) * HSTR + kb + akoff);
#pragma unroll
            for (int ntp = 0; ntp < 4; ntp++)
                ldsm4(b[ntp], Bs + (bnrow + ntp * 16) * HSTR + kb + bkoff);
#pragma unroll
            for (int mt = 0; mt < MTC; mt++)
#pragma unroll
                for (int ntp = 0; ntp < 4; ntp++) {
                    mma16816(acc[mt][2 * ntp],     a[mt], &b[ntp][0]);
                    mma16816(acc[mt][2 * ntp + 1], a[mt], &b[ntp][2]);
                }
        }
        stg = (stg + 1 >= NSTG) ? 0 : stg + 1;
    }

    // epilogue: d0:(r,c) d1:(r,c+1) d2:(r+8,c) d3:(r+8,c+1)
#pragma unroll
    for (int mt = 0; mt < MTC; mt++) {
#pragma unroll
        for (int half = 0; half < 2; half++) {
            int row = blockRow + wm * (MT / 4) + mt * 16 + qrow + half * 8;
            int bch = row >> 12;
            int orow = row;
            if (permute) {
                int rem = row & 4095;
                orow = ((bch << 4) + (rem & 15)) * NN + (rem >> 4);
            }
            float* crow = Cf ? Cf + (size_t)orow * Nc : nullptr;
            __half* hrow = Ch ? Ch + (size_t)orow * Nc : nullptr;
            const float* arow = addsrc ? addsrc + (size_t)orow * Nc : nullptr;
#pragma unroll
            for (int nt = 0; nt < 8; nt++) {
#pragma unroll
                for (int e = 0; e < 2; e++) {
                    int col = blockCol + wn * 64 + nt * 8 + 2 * qk + e;
                    float v = acc[mt][nt][half * 2 + e];
                    if (bias) v += bias[col];
                    if (act) {
                        float xg = v;
                        v = 0.5f * xg * (1.f + tanhf(0.7978845608028654f *
                                (xg + 0.044715f * xg * xg * xg)));
                    }
                    if (gate) v *= gate[bch * ADAW + col];
                    if (arow) v += arow[col];
                    if (crow) crow[col] = v;
                    if (hrow) hrow[col] = __float2half(v);
                }
            }
        }
    }
}

#define TCG_SMEM_256 (NSTG * (256 + 128) * HSTR * 2)
#define TCG_SMEM_128 (NSTG * (128 + 128) * HSTR * 2)

// ---------------- ada = silu(c4t) @ W_ada + b_ada -------------------------
__global__ __launch_bounds__(128) void ada_kernel(
    const float* __restrict__ c4t, const float* __restrict__ W,
    const float* __restrict__ bias)
{
    __shared__ float ss[MM];
    int b = blockIdx.y;
    for (int i = threadIdx.x; i < MM; i += 128) {
        float v = c4t[b * MM + i];
        ss[i] = v / (1.f + expf(-v));
    }
    __syncthreads();
    int col = blockIdx.x * 128 + threadIdx.x;
    float acc = bias[col];
    for (int k = 0; k < MM; k++)
        acc += ss[k] * W[(size_t)k * ADAW + col];
    g_ada[b * ADAW + col] = acc;
}

// ---------------- rope tables ---------------------------------------------
__global__ void rope_kernel(const int* __restrict__ f)
{
    int idx = threadIdx.x;
    if (idx < TT * (DD / 2)) {
        int t = idx / (DD / 2), i = idx % (DD / 2);
        float pos = (float)f[t];
        float freq = powf(10000.f, -((2.f * (float)i) / (float)DD));
        float a = pos * freq;
        g_ropec[idx] = cosf(a);
        g_ropes[idx] = sinf(a);
    }
}

// ---------------- extra-KV projections ------------------------------------
__global__ __launch_bounds__(256) void ekv_kernel(
    const float* __restrict__ c,
    const float* __restrict__ tk, const float* __restrict__ tv,
    const float* __restrict__ sk, const float* __restrict__ sv)
{
    __shared__ float cs[MM];
    int row = blockIdx.x;
    int which = blockIdx.y;
    const float* W = (which == 0) ? tk : (which == 1) ? tv : (which == 2) ? sk : sv;
    float* O = (which == 0) ? g_tk : (which == 1) ? g_tv : (which == 2) ? g_sk : g_sv;
    for (int i = threadIdx.x; i < MM; i += 256) cs[i] = c[(size_t)row * MM + i];
    __syncthreads();
    for (int col = threadIdx.x; col < MM; col += 256) {
        float acc = 0.f;
        for (int k = 0; k < MM; k++)
            acc += cs[k] * W[(size_t)k * MM + col];
        O[(size_t)row * MM + col] = acc;
    }
}

// ---------------- LayerNorm (half output) ----------------------------------
__global__ __launch_bounds__(256) void ln_kernel(
    const float* __restrict__ X, __half* __restrict__ out, float* __restrict__ copyDst,
    const float* __restrict__ w, const float* __restrict__ bvec,
    const float* __restrict__ ada, int shOff, int scOff, float eps, int permute)
{
    int row = blockIdx.x;
    const float* xr = X + (size_t)row * MM;
    float xv[5];
    float s = 0.f, sq = 0.f;
    int k = 0;
    for (int i = threadIdx.x; i < MM; i += 256, k++) {
        float v = xr[i];
        xv[k] = v;
        s += v; sq += v * v;
    }
    __shared__ float reds[8], redq[8], stats[2];
    for (int off = 16; off > 0; off >>= 1) {
        s  += __shfl_xor_sync(0xffffffffu, s,  off);
        sq += __shfl_xor_sync(0xffffffffu, sq, off);
    }
    int wid = threadIdx.x >> 5, lane = threadIdx.x & 31;
    if (lane == 0) { reds[wid] = s; redq[wid] = sq; }
    __syncthreads();
    if (threadIdx.x == 0) {
        float ts = 0.f, tq = 0.f;
        for (int i2 = 0; i2 < 8; i2++) { ts += reds[i2]; tq += redq[i2]; }
        float mean = ts * (1.f / MM);
        float var = tq * (1.f / MM) - mean * mean;
        stats[0] = mean;
        stats[1] = rsqrtf(var + eps);
    }
    __syncthreads();
    float mean = stats[0], rstd = stats[1];
    int b = row >> 12;
    int orow = row;
    if (permute) {
        int rem = row & 4095;
        int t = rem >> 8, n = rem & 255;
        orow = ((b << 8) + n) * TT + t;
    }
    k = 0;
    for (int i = threadIdx.x; i < MM; i += 256, k++) {
        float v = xv[k];
        float nv = (v - mean) * rstd;
        float y;
        if (ada) y = nv * (1.f + ada[b * ADAW + scOff + i]) + ada[b * ADAW + shOff + i];
        else     y = nv * w[i] + bvec[i];
        out[(size_t)orow * MM + i] = __float2half(y);
        if (copyDst) copyDst[(size_t)row * MM + i] = v;
    }
}

// ---------------- temporal attention (half qkv in, half out) ---------------
__global__ __launch_bounds__(256) void attn_t_kernel()
{
    __shared__ float qs[TT * DD];
    __shared__ float kks[2 * TT * DD];
    __shared__ float vvs[2 * TT * DD];
    __shared__ float scs[TT * 2 * TT];
    int h = blockIdx.x, n = blockIdx.y, b = blockIdx.z;
    const __half* base = g_bigh + (size_t)((b * NN + n) * TT) * QKVW + h * DD;

    for (int idx = threadIdx.x; idx < TT * (DD / 2); idx += 256) {
        int t = idx / (DD / 2), i = idx % (DD / 2);
        float cc = g_ropec[idx], ssn = g_ropes[idx];
        const __half* qr = base + (size_t)t * QKVW + 2 * i;
        float x0 = __half2float(qr[0]), x1 = __half2float(qr[1]);
        qs[t * DD + 2 * i]     = SCALE * (x0 * cc - x1 * ssn);
        qs[t * DD + 2 * i + 1] = SCALE * (x1 * cc + x0 * ssn);
        const __half* kr = qr + MM;
        x0 = __half2float(kr[0]); x1 = __half2float(kr[1]);
        kks[(TT + t) * DD + 2 * i]     = x0 * cc - x1 * ssn;
        kks[(TT + t) * DD + 2 * i + 1] = x1 * cc + x0 * ssn;
        const float* er = g_tk + (size_t)(b * TT + t) * MM + h * DD + 2 * i;
        x0 = er[0]; x1 = er[1];
        kks[t * DD + 2 * i]     = x0 * cc - x1 * ssn;
        kks[t * DD + 2 * i + 1] = x1 * cc + x0 * ssn;
    }
    for (int idx = threadIdx.x; idx < TT * DD; idx += 256) {
        int t = idx / DD, d = idx % DD;
        vvs[(TT + t) * DD + d] = __half2float(base[(size_t)t * QKVW + 2 * MM + d]);
        vvs[t * DD + d] = g_tv[(size_t)(b * TT + t) * MM + h * DD + d];
    }
    __syncthreads();

    for (int idx = threadIdx.x; idx < TT * 2 * TT; idx += 256) {
        int t = idx / (2 * TT), j = idx % (2 * TT);
        float acc = 0.f;
#pragma unroll
        for (int d = 0; d < DD; d++) acc += qs[t * DD + d] * kks[j * DD + d];
        scs[idx] = acc;
    }
    __syncthreads();

    if (threadIdx.x < TT) {
        int t = threadIdx.x;
        float m = -1e30f;
        for (int j = 0; j < 2 * TT; j++) m = fmaxf(m, scs[t * 2 * TT + j]);
        float sum = 0.f;
        for (int j = 0; j < 2 * TT; j++) {
            float p = __expf(scs[t * 2 * TT + j] - m);
            scs[t * 2 * TT + j] = p;
            sum += p;
        }
        float inv = 1.f / sum;
        for (int j = 0; j < 2 * TT; j++) scs[t * 2 * TT + j] *= inv;
    }
    __syncthreads();

    for (int idx = threadIdx.x; idx < TT * DD; idx += 256) {
        int t = idx / DD, d = idx % DD;
        float acc = 0.f;
#pragma unroll
        for (int j = 0; j < 2 * TT; j++) acc += scs[t * 2 * TT + j] * vvs[j * DD + d];
        g_attnh[(size_t)((b * NN + n) * TT + t) * MM + h * DD + d] = __float2half(acc);
    }
}

// ---------------- spatial attention: online softmax, smem KV tiles ---------
#define SKV 64
__global__ __launch_bounds__(256) void attn_s_kernel()
{
    __shared__ __half kt[SKV * DD];
    __shared__ __half vt[SKV * DD];
    int h = blockIdx.x, t = blockIdx.y, b = blockIdx.z;
    int n = threadIdx.x;
    const __half* base = g_bigh + (size_t)((b * TT + t) * NN) * QKVW;

    uint32_t q2[DD / 2];
    {
        const uint32_t* qr = (const uint32_t*)(base + (size_t)n * QKVW + h * DD);
#pragma unroll
        for (int i = 0; i < DD / 2; i++) q2[i] = qr[i];
    }
    float acc[DD];
#pragma unroll
    for (int d = 0; d < DD; d++) acc[d] = 0.f;
    float mcur = -1e30f, lsum = 0.f;

    for (int tile = 0; tile < (NN + 1 + SKV - 1) / SKV; tile++) {
        int j0 = tile * SKV;
        int jcount = (NN + 1) - j0;
        if (jcount > SKV) jcount = SKV;
        __syncthreads();
        for (int idx = threadIdx.x; idx < jcount * (DD / 2); idx += 256) {
            int jj = idx / (DD / 2), dp = idx % (DD / 2);
            int j = j0 + jj;
            __half2 kv2, vv2;
            if (j == 0) {
                const float* kf = g_sk + (size_t)(b * TT + t) * MM + h * DD + 2 * dp;
                const float* vf = g_sv + (size_t)(b * TT + t) * MM + h * DD + 2 * dp;
                kv2 = __floats2half2_rn(kf[0], kf[1]);
                vv2 = __floats2half2_rn(vf[0], vf[1]);
            } else {
                const __half* krow = base + (size_t)(j - 1) * QKVW + MM + h * DD;
                const __half* vrow = base + (size_t)(j - 1) * QKVW + 2 * MM + h * DD;
                kv2 = *(const __half2*)(krow + 2 * dp);
                vv2 = *(const __half2*)(vrow + 2 * dp);
            }
            *(__half2*)&kt[jj * DD + 2 * dp] = kv2;
            *(__half2*)&vt[jj * DD + 2 * dp] = vv2;
        }
        __syncthreads();

        for (int jj = 0; jj < jcount; jj++) {
            float s = 0.f;
#pragma unroll
            for (int i = 0; i < DD / 2; i++) {
                float2 kp = __half22float2(*(const __half2*)&kt[jj * DD + 2 * i]);
                float2 qp = __half22float2(*(const __half2*)&q2[i]);
                s += qp.x * kp.x + qp.y * kp.y;
            }
            s *= SCALE;
            if (s > mcur) {
                float c = __expf(mcur - s);
                lsum *= c;
#pragma unroll
                for (int d = 0; d < DD; d++) acc[d] *= c;
                mcur = s;
            }
            float p = __expf(s - mcur);
            lsum += p;
#pragma unroll
            for (int i = 0; i < DD / 2; i++) {
                float2 vp = __half22float2(*(const __half2*)&vt[jj * DD + 2 * i]);
                acc[2 * i]     += p * vp.x;
                acc[2 * i + 1] += p * vp.y;
            }
        }
    }
    float inv = 1.f / lsum;
    __half* orow = g_attnh + (size_t)((b * TT + t) * NN + n) * MM + h * DD;
#pragma unroll
    for (int d = 0; d < DD; d++) orow[d] = __float2half(acc[d] * inv);
}

// ---------------- launch ----------------------------------------------------
extern "C" void kernel_launch(void* const* d_in, const int* in_sizes, int n_in,
                              void* d_out, int out_size)
{
    (void)in_sizes; (void)n_in; (void)out_size;
    const float* x      = (const float*)d_in[0];
    const float* c4t    = (const float*)d_in[1];
    const float* c      = (const float*)d_in[2];
    const float* W_ada  = (const float*)d_in[3];
    const float* b_ada  = (const float*)d_in[4];
    const float* tn_w   = (const float*)d_in[5];
    const float* tn_b   = (const float*)d_in[6];
    const float* t_qkv  = (const float*)d_in[7];
    const float* t_k    = (const float*)d_in[8];
    const float* t_v    = (const float*)d_in[9];
    const float* t_out  = (const float*)d_in[10];
    const float* t_fc_w = (const float*)d_in[11];
    const float* t_fc_b = (const float*)d_in[12];
    const float* s_qkv  = (const float*)d_in[13];
    const float* s_k    = (const float*)d_in[14];
    const float* s_v    = (const float*)d_in[15];
    const float* s_out  = (const float*)d_in[16];
    const float* mlp_w1 = (const float*)d_in[17];
    const float* mlp_b1 = (const float*)d_in[18];
    const float* mlp_w2 = (const float*)d_in[19];
    const float* mlp_b2 = (const float*)d_in[20];
    const int*   f      = (const int*)d_in[21];
    float* out = (float*)d_out;

    float *px4, *pada;
    __half *plnh, *pattnh, *pbigh;
    __half *wtq, *wtoutrm, *wtf, *wcomb, *wsq, *wso, *ww1, *ww2;
    cudaGetSymbolAddress((void**)&px4,    g_x4);
    cudaGetSymbolAddress((void**)&pada,   g_ada);
    cudaGetSymbolAddress((void**)&plnh,   g_lnh);
    cudaGetSymbolAddress((void**)&pattnh, g_attnh);
    cudaGetSymbolAddress((void**)&pbigh,  g_bigh);
    cudaGetSymbolAddress((void**)&wtq,    g_wh_tqkv);
    cudaGetSymbolAddress((void**)&wtoutrm,g_wh_toutrm);
    cudaGetSymbolAddress((void**)&wtf,    g_wh_tfc);
    cudaGetSymbolAddress((void**)&wcomb,  g_wh_comb);
    cudaGetSymbolAddress((void**)&wsq,    g_wh_sqkv);
    cudaGetSymbolAddress((void**)&wso,    g_wh_sout);
    cudaGetSymbolAddress((void**)&ww1,    g_wh_w1);
    cudaGetSymbolAddress((void**)&ww2,    g_wh_w2);

    cudaFuncSetAttribute(tc_gemm_kernel<256>,
                         cudaFuncAttributeMaxDynamicSharedMemorySize, TCG_SMEM_256);
    cudaFuncSetAttribute(tc_gemm_kernel<128>,
                         cudaFuncAttributeMaxDynamicSharedMemorySize, TCG_SMEM_128);

    // weight convert/transpose
    convw_kernel<<<dim3(QKVW / 32, MM / 32), dim3(32, 8)>>>(t_qkv, wtq, MM, QKVW);
    convh_kernel<<<(MM * MM + 255) / 256, 256>>>(t_out, wtoutrm, MM * MM);
    convw_kernel<<<dim3(MM / 32, MM / 32), dim3(32, 8)>>>(t_fc_w, wtf, MM, MM);
    convw_kernel<<<dim3(QKVW / 32, MM / 32), dim3(32, 8)>>>(s_qkv, wsq, MM, QKVW);
    convw_kernel<<<dim3(MM / 32, MM / 32), dim3(32, 8)>>>(s_out, wso, MM, MM);
    convw_kernel<<<dim3(MLPW / 32, MM / 32), dim3(32, 8)>>>(mlp_w1, ww1, MM, MLPW);
    convw_kernel<<<dim3(MM / 32, MLPW / 32), dim3(32, 8)>>>(mlp_w2, ww2, MLPW, MM);

    // Wc^T[n][k0] = sum_j t_fc^T[n][j] * t_out[k0][j]  -> combined weight [N][K]
    tc_gemm_kernel<128><<<dim3(MM / 128, MM / 128), 256, TCG_SMEM_128>>>(
        wtf, wtoutrm, nullptr, nullptr, nullptr, nullptr, wcomb, MM, MM, 0, 0);

    ada_kernel<<<dim3(ADAW / 128, BB), 128>>>(c4t, W_ada, b_ada);
    rope_kernel<<<1, TT * (DD / 2)>>>(f);
    ekv_kernel<<<dim3(BB * TT, 4), 256>>>(c, t_k, t_v, s_k, s_v);

    // temporal branch
    ln_kernel<<<ROWS, 256>>>(x, plnh, px4, tn_w, tn_b, nullptr, 0, 0, 1e-5f, 1);
    tc_gemm_kernel<256><<<dim3(QKVW / 128, ROWS / 256), 256, TCG_SMEM_256>>>(
        plnh, wtq, nullptr, nullptr, nullptr, nullptr, pbigh, MM, QKVW, 0, 0);
    attn_t_kernel<<<dim3(HH, NN, BB), 256>>>();
    // fused (attn @ t_out) @ t_fc_w + b + x4, permuted rows
    tc_gemm_kernel<256><<<dim3(MM / 128, ROWS / 256), 256, TCG_SMEM_256>>>(
        pattnh, wcomb, t_fc_b, px4, nullptr, px4, nullptr, MM, MM, 0, 1);

    // spatial branch
    ln_kernel<<<ROWS, 256>>>(px4, plnh, nullptr, nullptr, nullptr, pada, 0, MM, 1e-6f, 0);
    tc_gemm_kernel<256><<<dim3(QKVW / 128, ROWS / 256), 256, TCG_SMEM_256>>>(
        plnh, wsq, nullptr, nullptr, nullptr, nullptr, pbigh, MM, QKVW, 0, 0);
    attn_s_kernel<<<dim3(HH, TT, BB), 256>>>();
    tc_gemm_kernel<256><<<dim3(MM / 128, ROWS / 256), 256, TCG_SMEM_256>>>(
        pattnh, wso, nullptr, px4, pada + 2 * MM, px4, nullptr, MM, MM, 0, 0);

    // MLP
    ln_kernel<<<ROWS, 256>>>(px4, plnh, nullptr, nullptr, nullptr, pada, 3 * MM, 4 * MM, 1e-6f, 0);
    tc_gemm_kernel<256><<<dim3(MLPW / 128, ROWS / 256), 256, TCG_SMEM_256>>>(
        plnh, ww1, mlp_b1, nullptr, nullptr, nullptr, pbigh, MM, MLPW, 1, 0);
    tc_gemm_kernel<256><<<dim3(MM / 128, ROWS / 256), 256, TCG_SMEM_256>>>(
        pbigh, ww2, mlp_b2, px4, pada + 5 * MM, out, nullptr, MLPW, MM, 0, 0);
}

// round 15
// speedup vs baseline: 4.4353x; 4.4353x over previous
#include <cuda_runtime.h>
#include <cuda_fp16.h>
#include <cstdint>

#define BB 2
#define TT 16
#define NN 256
#define MM 1152
#define HH 16
#define DD 72
#define ROWS 8192
#define ADAW 6912
#define QKVW 3456
#define MLPW 4608
#define SCALE 0.11785113019775793f

// ---------------- scratch -----------------------------------------------
__device__ float  g_x4[ROWS * MM];
__device__ __half g_lnh[ROWS * MM];
__device__ __half g_attnh[ROWS * MM];
__device__ __half g_bigh[(size_t)ROWS * MLPW];
__device__ float  g_ada[BB * ADAW];
__device__ float  g_tk[BB * TT * MM];
__device__ float  g_tv[BB * TT * MM];
__device__ float  g_sk[BB * TT * MM];
__device__ float  g_sv[BB * TT * MM];
__device__ float  g_ropec[TT * (DD / 2)];
__device__ float  g_ropes[TT * (DD / 2)];
// half weights
__device__ __half g_wh_tqkv[(size_t)QKVW * MM];   // [N][K]
__device__ __half g_wh_toutrm[(size_t)MM * MM];   // t_out row-major (convert only)
__device__ __half g_wh_tfc[(size_t)MM * MM];      // t_fc^T [N][K]
__device__ __half g_wh_comb[(size_t)MM * MM];     // (t_out@t_fc)^T [N][K]
__device__ __half g_wh_sqkv[(size_t)QKVW * MM];
__device__ __half g_wh_sout[(size_t)MM * MM];
__device__ __half g_wh_w1[(size_t)MLPW * MM];
__device__ __half g_wh_w2[(size_t)MM * MLPW];

// ---------------- helpers -------------------------------------------------
__device__ __forceinline__ uint32_t s2u(const void* p) {
    uint32_t a;
    asm("{ .reg .u64 t; cvta.to.shared.u64 t, %1; cvt.u32.u64 %0, t; }"
        : "=r"(a) : "l"(p));
    return a;
}
__device__ __forceinline__ void cpa16(void* s, const void* g) {
    asm volatile("cp.async.cg.shared.global [%0], [%1], 16;" :: "r"(s2u(s)), "l"(g));
}
__device__ __forceinline__ void ldsm4(uint32_t* r, const void* p) {
    asm volatile("ldmatrix.sync.aligned.m8n8.x4.shared.b16 {%0,%1,%2,%3}, [%4];"
        : "=r"(r[0]), "=r"(r[1]), "=r"(r[2]), "=r"(r[3]) : "r"(s2u(p)));
}
__device__ __forceinline__ void mma16816(float* d, const uint32_t* a, const uint32_t* b) {
    asm volatile(
        "mma.sync.aligned.m16n8k16.row.col.f32.f16.f16.f32 "
        "{%0,%1,%2,%3},{%4,%5,%6,%7},{%8,%9},{%0,%1,%2,%3};"
        : "+f"(d[0]), "+f"(d[1]), "+f"(d[2]), "+f"(d[3])
        : "r"(a[0]), "r"(a[1]), "r"(a[2]), "r"(a[3]), "r"(b[0]), "r"(b[1]));
}

// ---------------- weight transpose+convert [K,N]f32 -> [N,K]h ------------
__global__ __launch_bounds__(256) void convw_kernel(
    const float* __restrict__ S, __half* __restrict__ D, int K, int N)
{
    __shared__ float t[32][33];
    int x = blockIdx.x * 32 + threadIdx.x;
    int y0 = blockIdx.y * 32;
#pragma unroll
    for (int j = threadIdx.y; j < 32; j += 8)
        t[j][threadIdx.x] = S[(size_t)(y0 + j) * N + x];
    __syncthreads();
    int x2 = y0 + threadIdx.x;
    int y2 = blockIdx.x * 32;
#pragma unroll
    for (int j = threadIdx.y; j < 32; j += 8)
        D[(size_t)(y2 + j) * K + x2] = __float2half(t[threadIdx.x][j]);
}

// ---------------- plain convert f32 -> half (same layout) ------------------
__global__ __launch_bounds__(256) void convh_kernel(
    const float* __restrict__ S, __half* __restrict__ D, int total)
{
    int i = blockIdx.x * 256 + threadIdx.x;
    if (i < total) D[i] = __float2half(S[i]);
}

// ---------------- fp16 mma GEMM: CTA 128x128, warp 32x64, Kc=64 ----------
// 3-stage cp.async ring (wait -> barrier -> prefetch -> compute), ldmatrix,
// 2 CTAs/SM. smem row stride 72 halves (144B -> bank stride 4): ldsm's
// 8 rows hit banks {0,4,...,28} - conflict-free.
#define HSTR 72
#define KC 64
#define TILE_H (128 * HSTR)            // halves per operand tile
#define STAGE_H (2 * TILE_H)           // A + B
#define NSTG 3
#define TCG_SMEM (NSTG * STAGE_H * 2)  // bytes (108 KB)
__global__ __launch_bounds__(256, 2) void tc_gemm_kernel(
    const __half* __restrict__ A, const __half* __restrict__ W,
    const float* __restrict__ bias, const float* __restrict__ addsrc,
    const float* __restrict__ gate,
    float* __restrict__ Cf, __half* __restrict__ Ch,
    int K, int Nc, int act, int permute)
{
    extern __shared__ __half smem[];
    int tid = threadIdx.x, lane = tid & 31, wid = tid >> 5;
    int wm = wid & 3, wn = wid >> 2;
    int qrow = lane >> 2, qk = lane & 3;
    int blockCol = blockIdx.x * 128, blockRow = blockIdx.y * 128;
    int nc = K >> 6;

    float acc[2][8][4];
#pragma unroll
    for (int mt = 0; mt < 2; mt++)
#pragma unroll
        for (int nt = 0; nt < 8; nt++)
#pragma unroll
            for (int r = 0; r < 4; r++) acc[mt][nt][r] = 0.f;

    const __half* Ab = A + (size_t)blockRow * K;
    const __half* Bb = W + (size_t)blockCol * K;

    // ldmatrix addresses (half offsets within tile)
    int amrow = wm * 32 + (lane & 15);
    int akoff = (lane >> 4) << 3;
    int bnrow = wn * 64 + (lane & 7) + ((lane >> 4) << 3);
    int bkoff = ((lane >> 3) & 1) << 3;

    // per chunk each operand = 128 rows x 8 segs of 16B; 4 segs/thread/operand
#define PREFETCH(chunk, stg_) do {                                              \
    __half* As_ = smem + (stg_) * STAGE_H;                                       \
    __half* Bs_ = As_ + TILE_H;                                                  \
    int k0 = (chunk) << 6;                                                       \
    _Pragma("unroll")                                                            \
    for (int j = 0; j < 4; j++) {                                                \
        int seg = tid + j * 256;                                                 \
        int r_ = seg >> 3, s_ = seg & 7;                                         \
        cpa16(As_ + r_ * HSTR + s_ * 8, Ab + (size_t)r_ * K + k0 + s_ * 8);      \
        cpa16(Bs_ + r_ * HSTR + s_ * 8, Bb + (size_t)r_ * K + k0 + s_ * 8);      \
    }                                                                            \
    asm volatile("cp.async.commit_group;" ::: "memory");                         \
} while (0)

    PREFETCH(0, 0);
    if (nc > 1) PREFETCH(1, 1);

    int stg = 0;
#pragma unroll 1
    for (int i = 0; i < nc; i++) {
        int rem = nc - 1 - i;
        if (rem >= 1) asm volatile("cp.async.wait_group 1;" ::: "memory");
        else          asm volatile("cp.async.wait_group 0;" ::: "memory");
        // ALL threads' copies for chunk i done; reads of stage (i-1) done:
        __syncthreads();
        if (i + 2 < nc)
            PREFETCH(i + 2, (stg + 2 >= NSTG) ? stg - 1 : stg + 2); // = (i-1)%3
        const __half* As = smem + stg * STAGE_H;
        const __half* Bs = As + TILE_H;
#pragma unroll
        for (int kk = 0; kk < 4; kk++) {
            int kb = kk * 16;
            uint32_t a[2][4], b[4][4];
            ldsm4(a[0], As + amrow * HSTR + kb + akoff);
            ldsm4(a[1], As + (amrow + 16) * HSTR + kb + akoff);
#pragma unroll
            for (int ntp = 0; ntp < 4; ntp++)
                ldsm4(b[ntp], Bs + (bnrow + ntp * 16) * HSTR + kb + bkoff);
#pragma unroll
            for (int mt = 0; mt < 2; mt++)
#pragma unroll
                for (int ntp = 0; ntp < 4; ntp++) {
                    mma16816(acc[mt][2 * ntp],     a[mt], &b[ntp][0]);
                    mma16816(acc[mt][2 * ntp + 1], a[mt], &b[ntp][2]);
                }
        }
        stg = (stg + 1 >= NSTG) ? 0 : stg + 1;
    }

    // epilogue: d0:(r,c) d1:(r,c+1) d2:(r+8,c) d3:(r+8,c+1)
#pragma unroll
    for (int mt = 0; mt < 2; mt++) {
#pragma unroll
        for (int half = 0; half < 2; half++) {
            int row = blockRow + wm * 32 + mt * 16 + qrow + half * 8;
            int bch = row >> 12;
            int orow = row;
            if (permute) {
                int rem = row & 4095;
                orow = ((bch << 4) + (rem & 15)) * NN + (rem >> 4);
            }
            float* crow = Cf ? Cf + (size_t)orow * Nc : nullptr;
            __half* hrow = Ch ? Ch + (size_t)orow * Nc : nullptr;
            const float* arow = addsrc ? addsrc + (size_t)orow * Nc : nullptr;
#pragma unroll
            for (int nt = 0; nt < 8; nt++) {
#pragma unroll
                for (int e = 0; e < 2; e++) {
                    int col = blockCol + wn * 64 + nt * 8 + 2 * qk + e;
                    float v = acc[mt][nt][half * 2 + e];
                    if (bias) v += bias[col];
                    if (act) {
                        float xg = v;
                        v = 0.5f * xg * (1.f + tanhf(0.7978845608028654f *
                                (xg + 0.044715f * xg * xg * xg)));
                    }
                    if (gate) v *= gate[bch * ADAW + col];
                    if (arow) v += arow[col];
                    if (crow) crow[col] = v;
                    if (hrow) hrow[col] = __float2half(v);
                }
            }
        }
    }
}

// ---------------- ada = silu(c4t) @ W_ada + b_ada -------------------------
__global__ __launch_bounds__(128) void ada_kernel(
    const float* __restrict__ c4t, const float* __restrict__ W,
    const float* __restrict__ bias)
{
    __shared__ float ss[MM];
    int b = blockIdx.y;
    for (int i = threadIdx.x; i < MM; i += 128) {
        float v = c4t[b * MM + i];
        ss[i] = v / (1.f + expf(-v));
    }
    __syncthreads();
    int col = blockIdx.x * 128 + threadIdx.x;
    float acc = bias[col];
    for (int k = 0; k < MM; k++)
        acc += ss[k] * W[(size_t)k * ADAW + col];
    g_ada[b * ADAW + col] = acc;
}

// ---------------- rope tables ---------------------------------------------
__global__ void rope_kernel(const int* __restrict__ f)
{
    int idx = threadIdx.x;
    if (idx < TT * (DD / 2)) {
        int t = idx / (DD / 2), i = idx % (DD / 2);
        float pos = (float)f[t];
        float freq = powf(10000.f, -((2.f * (float)i) / (float)DD));
        float a = pos * freq;
        g_ropec[idx] = cosf(a);
        g_ropes[idx] = sinf(a);
    }
}

// ---------------- extra-KV projections ------------------------------------
__global__ __launch_bounds__(256) void ekv_kernel(
    const float* __restrict__ c,
    const float* __restrict__ tk, const float* __restrict__ tv,
    const float* __restrict__ sk, const float* __restrict__ sv)
{
    __shared__ float cs[MM];
    int row = blockIdx.x;
    int which = blockIdx.y;
    const float* W = (which == 0) ? tk : (which == 1) ? tv : (which == 2) ? sk : sv;
    float* O = (which == 0) ? g_tk : (which == 1) ? g_tv : (which == 2) ? g_sk : g_sv;
    for (int i = threadIdx.x; i < MM; i += 256) cs[i] = c[(size_t)row * MM + i];
    __syncthreads();
    for (int col = threadIdx.x; col < MM; col += 256) {
        float acc = 0.f;
        for (int k = 0; k < MM; k++)
            acc += cs[k] * W[(size_t)k * MM + col];
        O[(size_t)row * MM + col] = acc;
    }
}

// ---------------- LayerNorm (half output) ----------------------------------
__global__ __launch_bounds__(256) void ln_kernel(
    const float* __restrict__ X, __half* __restrict__ out, float* __restrict__ copyDst,
    const float* __restrict__ w, const float* __restrict__ bvec,
    const float* __restrict__ ada, int shOff, int scOff, float eps, int permute)
{
    int row = blockIdx.x;
    const float* xr = X + (size_t)row * MM;
    float xv[5];
    float s = 0.f, sq = 0.f;
    int k = 0;
    for (int i = threadIdx.x; i < MM; i += 256, k++) {
        float v = xr[i];
        xv[k] = v;
        s += v; sq += v * v;
    }
    __shared__ float reds[8], redq[8], stats[2];
    for (int off = 16; off > 0; off >>= 1) {
        s  += __shfl_xor_sync(0xffffffffu, s,  off);
        sq += __shfl_xor_sync(0xffffffffu, sq, off);
    }
    int wid = threadIdx.x >> 5, lane = threadIdx.x & 31;
    if (lane == 0) { reds[wid] = s; redq[wid] = sq; }
    __syncthreads();
    if (threadIdx.x == 0) {
        float ts = 0.f, tq = 0.f;
        for (int i2 = 0; i2 < 8; i2++) { ts += reds[i2]; tq += redq[i2]; }
        float mean = ts * (1.f / MM);
        float var = tq * (1.f / MM) - mean * mean;
        stats[0] = mean;
        stats[1] = rsqrtf(var + eps);
    }
    __syncthreads();
    float mean = stats[0], rstd = stats[1];
    int b = row >> 12;
    int orow = row;
    if (permute) {
        int rem = row & 4095;
        int t = rem >> 8, n = rem & 255;
        orow = ((b << 8) + n) * TT + t;
    }
    k = 0;
    for (int i = threadIdx.x; i < MM; i += 256, k++) {
        float v = xv[k];
        float nv = (v - mean) * rstd;
        float y;
        if (ada) y = nv * (1.f + ada[b * ADAW + scOff + i]) + ada[b * ADAW + shOff + i];
        else     y = nv * w[i] + bvec[i];
        out[(size_t)orow * MM + i] = __float2half(y);
        if (copyDst) copyDst[(size_t)row * MM + i] = v;
    }
}

// ---------------- temporal attention (half qkv in, half out) ---------------
__global__ __launch_bounds__(256) void attn_t_kernel()
{
    __shared__ float qs[TT * DD];
    __shared__ float kks[2 * TT * DD];
    __shared__ float vvs[2 * TT * DD];
    __shared__ float scs[TT * 2 * TT];
    int h = blockIdx.x, n = blockIdx.y, b = blockIdx.z;
    const __half* base = g_bigh + (size_t)((b * NN + n) * TT) * QKVW + h * DD;

    for (int idx = threadIdx.x; idx < TT * (DD / 2); idx += 256) {
        int t = idx / (DD / 2), i = idx % (DD / 2);
        float cc = g_ropec[idx], ssn = g_ropes[idx];
        const __half* qr = base + (size_t)t * QKVW + 2 * i;
        float x0 = __half2float(qr[0]), x1 = __half2float(qr[1]);
        qs[t * DD + 2 * i]     = SCALE * (x0 * cc - x1 * ssn);
        qs[t * DD + 2 * i + 1] = SCALE * (x1 * cc + x0 * ssn);
        const __half* kr = qr + MM;
        x0 = __half2float(kr[0]); x1 = __half2float(kr[1]);
        kks[(TT + t) * DD + 2 * i]     = x0 * cc - x1 * ssn;
        kks[(TT + t) * DD + 2 * i + 1] = x1 * cc + x0 * ssn;
        const float* er = g_tk + (size_t)(b * TT + t) * MM + h * DD + 2 * i;
        x0 = er[0]; x1 = er[1];
        kks[t * DD + 2 * i]     = x0 * cc - x1 * ssn;
        kks[t * DD + 2 * i + 1] = x1 * cc + x0 * ssn;
    }
    for (int idx = threadIdx.x; idx < TT * DD; idx += 256) {
        int t = idx / DD, d = idx % DD;
        vvs[(TT + t) * DD + d] = __half2float(base[(size_t)t * QKVW + 2 * MM + d]);
        vvs[t * DD + d] = g_tv[(size_t)(b * TT + t) * MM + h * DD + d];
    }
    __syncthreads();

    for (int idx = threadIdx.x; idx < TT * 2 * TT; idx += 256) {
        int t = idx / (2 * TT), j = idx % (2 * TT);
        float acc = 0.f;
#pragma unroll
        for (int d = 0; d < DD; d++) acc += qs[t * DD + d] * kks[j * DD + d];
        scs[idx] = acc;
    }
    __syncthreads();

    if (threadIdx.x < TT) {
        int t = threadIdx.x;
        float m = -1e30f;
        for (int j = 0; j < 2 * TT; j++) m = fmaxf(m, scs[t * 2 * TT + j]);
        float sum = 0.f;
        for (int j = 0; j < 2 * TT; j++) {
            float p = __expf(scs[t * 2 * TT + j] - m);
            scs[t * 2 * TT + j] = p;
            sum += p;
        }
        float inv = 1.f / sum;
        for (int j = 0; j < 2 * TT; j++) scs[t * 2 * TT + j] *= inv;
    }
    __syncthreads();

    for (int idx = threadIdx.x; idx < TT * DD; idx += 256) {
        int t = idx / DD, d = idx % DD;
        float acc = 0.f;
#pragma unroll
        for (int j = 0; j < 2 * TT; j++) acc += scs[t * 2 * TT + j] * vvs[j * DD + d];
        g_attnh[(size_t)((b * NN + n) * TT + t) * MM + h * DD + d] = __float2half(acc);
    }
}

// ---------------- spatial attention: online softmax, smem KV tiles ---------
#define SKV 64
__global__ __launch_bounds__(256) void attn_s_kernel()
{
    __shared__ __half kt[SKV * DD];
    __shared__ __half vt[SKV * DD];
    int h = blockIdx.x, t = blockIdx.y, b = blockIdx.z;
    int n = threadIdx.x;
    const __half* base = g_bigh + (size_t)((b * TT + t) * NN) * QKVW;

    uint32_t q2[DD / 2];
    {
        const uint32_t* qr = (const uint32_t*)(base + (size_t)n * QKVW + h * DD);
#pragma unroll
        for (int i = 0; i < DD / 2; i++) q2[i] = qr[i];
    }
    float acc[DD];
#pragma unroll
    for (int d = 0; d < DD; d++) acc[d] = 0.f;
    float mcur = -1e30f, lsum = 0.f;

    for (int tile = 0; tile < (NN + 1 + SKV - 1) / SKV; tile++) {
        int j0 = tile * SKV;
        int jcount = (NN + 1) - j0;
        if (jcount > SKV) jcount = SKV;
        __syncthreads();
        for (int idx = threadIdx.x; idx < jcount * (DD / 2); idx += 256) {
            int jj = idx / (DD / 2), dp = idx % (DD / 2);
            int j = j0 + jj;
            __half2 kv2, vv2;
            if (j == 0) {
                const float* kf = g_sk + (size_t)(b * TT + t) * MM + h * DD + 2 * dp;
                const float* vf = g_sv + (size_t)(b * TT + t) * MM + h * DD + 2 * dp;
                kv2 = __floats2half2_rn(kf[0], kf[1]);
                vv2 = __floats2half2_rn(vf[0], vf[1]);
            } else {
                const __half* krow = base + (size_t)(j - 1) * QKVW + MM + h * DD;
                const __half* vrow = base + (size_t)(j - 1) * QKVW + 2 * MM + h * DD;
                kv2 = *(const __half2*)(krow + 2 * dp);
                vv2 = *(const __half2*)(vrow + 2 * dp);
            }
            *(__half2*)&kt[jj * DD + 2 * dp] = kv2;
            *(__half2*)&vt[jj * DD + 2 * dp] = vv2;
        }
        __syncthreads();

        for (int jj = 0; jj < jcount; jj++) {
            float s = 0.f;
#pragma unroll
            for (int i = 0; i < DD / 2; i++) {
                float2 kp = __half22float2(*(const __half2*)&kt[jj * DD + 2 * i]);
                float2 qp = __half22float2(*(const __half2*)&q2[i]);
                s += qp.x * kp.x + qp.y * kp.y;
            }
            s *= SCALE;
            if (s > mcur) {
                float c = __expf(mcur - s);
                lsum *= c;
#pragma unroll
                for (int d = 0; d < DD; d++) acc[d] *= c;
                mcur = s;
            }
            float p = __expf(s - mcur);
            lsum += p;
#pragma unroll
            for (int i = 0; i < DD / 2; i++) {
                float2 vp = __half22float2(*(const __half2*)&vt[jj * DD + 2 * i]);
                acc[2 * i]     += p * vp.x;
                acc[2 * i + 1] += p * vp.y;
            }
        }
    }
    float inv = 1.f / lsum;
    __half* orow = g_attnh + (size_t)((b * TT + t) * NN + n) * MM + h * DD;
#pragma unroll
    for (int d = 0; d < DD; d++) orow[d] = __float2half(acc[d] * inv);
}

// ---------------- launch ----------------------------------------------------
extern "C" void kernel_launch(void* const* d_in, const int* in_sizes, int n_in,
                              void* d_out, int out_size)
{
    (void)in_sizes; (void)n_in; (void)out_size;
    const float* x      = (const float*)d_in[0];
    const float* c4t    = (const float*)d_in[1];
    const float* c      = (const float*)d_in[2];
    const float* W_ada  = (const float*)d_in[3];
    const float* b_ada  = (const float*)d_in[4];
    const float* tn_w   = (const float*)d_in[5];
    const float* tn_b   = (const float*)d_in[6];
    const float* t_qkv  = (const float*)d_in[7];
    const float* t_k    = (const float*)d_in[8];
    const float* t_v    = (const float*)d_in[9];
    const float* t_out  = (const float*)d_in[10];
    const float* t_fc_w = (const float*)d_in[11];
    const float* t_fc_b = (const float*)d_in[12];
    const float* s_qkv  = (const float*)d_in[13];
    const float* s_k    = (const float*)d_in[14];
    const float* s_v    = (const float*)d_in[15];
    const float* s_out  = (const float*)d_in[16];
    const float* mlp_w1 = (const float*)d_in[17];
    const float* mlp_b1 = (const float*)d_in[18];
    const float* mlp_w2 = (const float*)d_in[19];
    const float* mlp_b2 = (const float*)d_in[20];
    const int*   f      = (const int*)d_in[21];
    float* out = (float*)d_out;

    float *px4, *pada;
    __half *plnh, *pattnh, *pbigh;
    __half *wtq, *wtoutrm, *wtf, *wcomb, *wsq, *wso, *ww1, *ww2;
    cudaGetSymbolAddress((void**)&px4,    g_x4);
    cudaGetSymbolAddress((void**)&pada,   g_ada);
    cudaGetSymbolAddress((void**)&plnh,   g_lnh);
    cudaGetSymbolAddress((void**)&pattnh, g_attnh);
    cudaGetSymbolAddress((void**)&pbigh,  g_bigh);
    cudaGetSymbolAddress((void**)&wtq,    g_wh_tqkv);
    cudaGetSymbolAddress((void**)&wtoutrm,g_wh_toutrm);
    cudaGetSymbolAddress((void**)&wtf,    g_wh_tfc);
    cudaGetSymbolAddress((void**)&wcomb,  g_wh_comb);
    cudaGetSymbolAddress((void**)&wsq,    g_wh_sqkv);
    cudaGetSymbolAddress((void**)&wso,    g_wh_sout);
    cudaGetSymbolAddress((void**)&ww1,    g_wh_w1);
    cudaGetSymbolAddress((void**)&ww2,    g_wh_w2);

    cudaFuncSetAttribute(tc_gemm_kernel,
                         cudaFuncAttributeMaxDynamicSharedMemorySize, TCG_SMEM);

    // weight convert/transpose
    convw_kernel<<<dim3(QKVW / 32, MM / 32), dim3(32, 8)>>>(t_qkv, wtq, MM, QKVW);
    convh_kernel<<<(MM * MM + 255) / 256, 256>>>(t_out, wtoutrm, MM * MM);
    convw_kernel<<<dim3(MM / 32, MM / 32), dim3(32, 8)>>>(t_fc_w, wtf, MM, MM);
    convw_kernel<<<dim3(QKVW / 32, MM / 32), dim3(32, 8)>>>(s_qkv, wsq, MM, QKVW);
    convw_kernel<<<dim3(MM / 32, MM / 32), dim3(32, 8)>>>(s_out, wso, MM, MM);
    convw_kernel<<<dim3(MLPW / 32, MM / 32), dim3(32, 8)>>>(mlp_w1, ww1, MM, MLPW);
    convw_kernel<<<dim3(MM / 32, MLPW / 32), dim3(32, 8)>>>(mlp_w2, ww2, MLPW, MM);

    // Wc^T[n][k0] = sum_j t_fc^T[n][j] * t_out[k0][j]  -> combined weight [N][K]
    tc_gemm_kernel<<<dim3(MM / 128, MM / 128), 256, TCG_SMEM>>>(
        wtf, wtoutrm, nullptr, nullptr, nullptr, nullptr, wcomb, MM, MM, 0, 0);

    ada_kernel<<<dim3(ADAW / 128, BB), 128>>>(c4t, W_ada, b_ada);
    rope_kernel<<<1, TT * (DD / 2)>>>(f);
    ekv_kernel<<<dim3(BB * TT, 4), 256>>>(c, t_k, t_v, s_k, s_v);

    // temporal branch
    ln_kernel<<<ROWS, 256>>>(x, plnh, px4, tn_w, tn_b, nullptr, 0, 0, 1e-5f, 1);
    tc_gemm_kernel<<<dim3(QKVW / 128, ROWS / 128), 256, TCG_SMEM>>>(
        plnh, wtq, nullptr, nullptr, nullptr, nullptr, pbigh, MM, QKVW, 0, 0);
    attn_t_kernel<<<dim3(HH, NN, BB), 256>>>();
    // fused (attn @ t_out) @ t_fc_w + b + x4, permuted rows
    tc_gemm_kernel<<<dim3(MM / 128, ROWS / 128), 256, TCG_SMEM>>>(
        pattnh, wcomb, t_fc_b, px4, nullptr, px4, nullptr, MM, MM, 0, 1);

    // spatial branch
    ln_kernel<<<ROWS, 256>>>(px4, plnh, nullptr, nullptr, nullptr, pada, 0, MM, 1e-6f, 0);
    tc_gemm_kernel<<<dim3(QKVW / 128, ROWS / 128), 256, TCG_SMEM>>>(
        plnh, wsq, nullptr, nullptr, nullptr, nullptr, pbigh, MM, QKVW, 0, 0);
    attn_s_kernel<<<dim3(HH, TT, BB), 256>>>();
    tc_gemm_kernel<<<dim3(MM / 128, ROWS / 128), 256, TCG_SMEM>>>(
        pattnh, wso, nullptr, px4, pada + 2 * MM, px4, nullptr, MM, MM, 0, 0);

    // MLP
    ln_kernel<<<ROWS, 256>>>(px4, plnh, nullptr, nullptr, nullptr, pada, 3 * MM, 4 * MM, 1e-6f, 0);
    tc_gemm_kernel<<<dim3(MLPW / 128, ROWS / 128), 256, TCG_SMEM>>>(
        plnh, ww1, mlp_b1, nullptr, nullptr, nullptr, pbigh, MM, MLPW, 1, 0);
    tc_gemm_kernel<<<dim3(MM / 128, ROWS / 128), 256, TCG_SMEM>>>(
        pbigh, ww2, mlp_b2, px4, pada + 5 * MM, out, nullptr, MLPW, MM, 0, 0);
}

// round 16
// speedup vs baseline: 4.6734x; 1.0537x over previous
#include <cuda_runtime.h>
#include <cuda_fp16.h>
#include <cstdint>

#define BB 2
#define TT 16
#define NN 256
#define MM 1152
#define HH 16
#define DD 72
#define ROWS 8192
#define ADAW 6912
#define QKVW 3456
#define MLPW 4608
#define SCALE 0.11785113019775793f

// ---------------- scratch -----------------------------------------------
__device__ float  g_x4[ROWS * MM];
__device__ __half g_lnh[ROWS * MM];
__device__ __half g_attnh[ROWS * MM];
__device__ __half g_bigh[(size_t)ROWS * MLPW];
__device__ float  g_ada[BB * ADAW];
__device__ float  g_tk[BB * TT * MM];
__device__ float  g_tv[BB * TT * MM];
__device__ float  g_sk[BB * TT * MM];
__device__ float  g_sv[BB * TT * MM];
__device__ float  g_ropec[TT * (DD / 2)];
__device__ float  g_ropes[TT * (DD / 2)];
// half weights
__device__ __half g_wh_tqkv[(size_t)QKVW * MM];   // [N][K]
__device__ __half g_wh_toutrm[(size_t)MM * MM];   // t_out row-major (convert only)
__device__ __half g_wh_tfc[(size_t)MM * MM];      // t_fc^T [N][K]
__device__ __half g_wh_comb[(size_t)MM * MM];     // (t_out@t_fc)^T [N][K]
__device__ __half g_wh_sqkv[(size_t)QKVW * MM];
__device__ __half g_wh_sout[(size_t)MM * MM];
__device__ __half g_wh_w1[(size_t)MLPW * MM];
__device__ __half g_wh_w2[(size_t)MM * MLPW];

// ---------------- helpers -------------------------------------------------
__device__ __forceinline__ uint32_t s2u(const void* p) {
    uint32_t a;
    asm("{ .reg .u64 t; cvta.to.shared.u64 t, %1; cvt.u32.u64 %0, t; }"
        : "=r"(a) : "l"(p));
    return a;
}
__device__ __forceinline__ void cpa16(void* s, const void* g) {
    asm volatile("cp.async.cg.shared.global [%0], [%1], 16;" :: "r"(s2u(s)), "l"(g));
}
__device__ __forceinline__ void ldsm4(uint32_t* r, const void* p) {
    asm volatile("ldmatrix.sync.aligned.m8n8.x4.shared.b16 {%0,%1,%2,%3}, [%4];"
        : "=r"(r[0]), "=r"(r[1]), "=r"(r[2]), "=r"(r[3]) : "r"(s2u(p)));
}
__device__ __forceinline__ void mma16816(float* d, const uint32_t* a, const uint32_t* b) {
    asm volatile(
        "mma.sync.aligned.m16n8k16.row.col.f32.f16.f16.f32 "
        "{%0,%1,%2,%3},{%4,%5,%6,%7},{%8,%9},{%0,%1,%2,%3};"
        : "+f"(d[0]), "+f"(d[1]), "+f"(d[2]), "+f"(d[3])
        : "r"(a[0]), "r"(a[1]), "r"(a[2]), "r"(a[3]), "r"(b[0]), "r"(b[1]));
}
// packed f32x2 (Blackwell FFMA2)
__device__ __forceinline__ unsigned long long packf2(float x, float y) {
    unsigned long long u;
    asm("mov.b64 %0, {%1, %2};" : "=l"(u) : "f"(x), "f"(y));
    return u;
}
__device__ __forceinline__ float2 unpackf2(unsigned long long u) {
    float2 v;
    asm("mov.b64 {%0, %1}, %2;" : "=f"(v.x), "=f"(v.y) : "l"(u));
    return v;
}
__device__ __forceinline__ void ffma2(unsigned long long& d,
                                      unsigned long long a, unsigned long long b) {
    asm("fma.rn.f32x2 %0, %1, %2, %3;" : "=l"(d) : "l"(a), "l"(b), "l"(d));
}
__device__ __forceinline__ void fmul2(unsigned long long& d,
                                      unsigned long long a, unsigned long long b) {
    asm("mul.rn.f32x2 %0, %1, %2;" : "=l"(d) : "l"(a), "l"(b));
}

// ---------------- weight transpose+convert [K,N]f32 -> [N,K]h ------------
__global__ __launch_bounds__(256) void convw_kernel(
    const float* __restrict__ S, __half* __restrict__ D, int K, int N)
{
    __shared__ float t[32][33];
    int x = blockIdx.x * 32 + threadIdx.x;
    int y0 = blockIdx.y * 32;
#pragma unroll
    for (int j = threadIdx.y; j < 32; j += 8)
        t[j][threadIdx.x] = S[(size_t)(y0 + j) * N + x];
    __syncthreads();
    int x2 = y0 + threadIdx.x;
    int y2 = blockIdx.x * 32;
#pragma unroll
    for (int j = threadIdx.y; j < 32; j += 8)
        D[(size_t)(y2 + j) * K + x2] = __float2half(t[threadIdx.x][j]);
}

// ---------------- plain convert f32 -> half (same layout) ------------------
__global__ __launch_bounds__(256) void convh_kernel(
    const float* __restrict__ S, __half* __restrict__ D, int total)
{
    int i = blockIdx.x * 256 + threadIdx.x;
    if (i < total) D[i] = __float2half(S[i]);
}

// ---------------- fp16 mma GEMM: CTA 128x128, warp 32x64, Kc=64 ----------
// (identical to round-15 passing version)
#define HSTR 72
#define TILE_H (128 * HSTR)
#define STAGE_H (2 * TILE_H)
#define NSTG 3
#define TCG_SMEM (NSTG * STAGE_H * 2)
__global__ __launch_bounds__(256, 2) void tc_gemm_kernel(
    const __half* __restrict__ A, const __half* __restrict__ W,
    const float* __restrict__ bias, const float* __restrict__ addsrc,
    const float* __restrict__ gate,
    float* __restrict__ Cf, __half* __restrict__ Ch,
    int K, int Nc, int act, int permute)
{
    extern __shared__ __half smem[];
    int tid = threadIdx.x, lane = tid & 31, wid = tid >> 5;
    int wm = wid & 3, wn = wid >> 2;
    int qrow = lane >> 2, qk = lane & 3;
    int blockCol = blockIdx.x * 128, blockRow = blockIdx.y * 128;
    int nc = K >> 6;

    float acc[2][8][4];
#pragma unroll
    for (int mt = 0; mt < 2; mt++)
#pragma unroll
        for (int nt = 0; nt < 8; nt++)
#pragma unroll
            for (int r = 0; r < 4; r++) acc[mt][nt][r] = 0.f;

    const __half* Ab = A + (size_t)blockRow * K;
    const __half* Bb = W + (size_t)blockCol * K;

    int amrow = wm * 32 + (lane & 15);
    int akoff = (lane >> 4) << 3;
    int bnrow = wn * 64 + (lane & 7) + ((lane >> 4) << 3);
    int bkoff = ((lane >> 3) & 1) << 3;

#define PREFETCH(chunk, stg_) do {                                              \
    __half* As_ = smem + (stg_) * STAGE_H;                                       \
    __half* Bs_ = As_ + TILE_H;                                                  \
    int k0 = (chunk) << 6;                                                       \
    _Pragma("unroll")                                                            \
    for (int j = 0; j < 4; j++) {                                                \
        int seg = tid + j * 256;                                                 \
        int r_ = seg >> 3, s_ = seg & 7;                                         \
        cpa16(As_ + r_ * HSTR + s_ * 8, Ab + (size_t)r_ * K + k0 + s_ * 8);      \
        cpa16(Bs_ + r_ * HSTR + s_ * 8, Bb + (size_t)r_ * K + k0 + s_ * 8);      \
    }                                                                            \
    asm volatile("cp.async.commit_group;" ::: "memory");                         \
} while (0)

    PREFETCH(0, 0);
    if (nc > 1) PREFETCH(1, 1);

    int stg = 0;
#pragma unroll 1
    for (int i = 0; i < nc; i++) {
        int rem = nc - 1 - i;
        if (rem >= 1) asm volatile("cp.async.wait_group 1;" ::: "memory");
        else          asm volatile("cp.async.wait_group 0;" ::: "memory");
        __syncthreads();
        if (i + 2 < nc)
            PREFETCH(i + 2, (stg + 2 >= NSTG) ? stg - 1 : stg + 2);
        const __half* As = smem + stg * STAGE_H;
        const __half* Bs = As + TILE_H;
#pragma unroll
        for (int kk = 0; kk < 4; kk++) {
            int kb = kk * 16;
            uint32_t a[2][4], b[4][4];
            ldsm4(a[0], As + amrow * HSTR + kb + akoff);
            ldsm4(a[1], As + (amrow + 16) * HSTR + kb + akoff);
#pragma unroll
            for (int ntp = 0; ntp < 4; ntp++)
                ldsm4(b[ntp], Bs + (bnrow + ntp * 16) * HSTR + kb + bkoff);
#pragma unroll
            for (int mt = 0; mt < 2; mt++)
#pragma unroll
                for (int ntp = 0; ntp < 4; ntp++) {
                    mma16816(acc[mt][2 * ntp],     a[mt], &b[ntp][0]);
                    mma16816(acc[mt][2 * ntp + 1], a[mt], &b[ntp][2]);
                }
        }
        stg = (stg + 1 >= NSTG) ? 0 : stg + 1;
    }

#pragma unroll
    for (int mt = 0; mt < 2; mt++) {
#pragma unroll
        for (int half = 0; half < 2; half++) {
            int row = blockRow + wm * 32 + mt * 16 + qrow + half * 8;
            int bch = row >> 12;
            int orow = row;
            if (permute) {
                int rem = row & 4095;
                orow = ((bch << 4) + (rem & 15)) * NN + (rem >> 4);
            }
            float* crow = Cf ? Cf + (size_t)orow * Nc : nullptr;
            __half* hrow = Ch ? Ch + (size_t)orow * Nc : nullptr;
            const float* arow = addsrc ? addsrc + (size_t)orow * Nc : nullptr;
#pragma unroll
            for (int nt = 0; nt < 8; nt++) {
#pragma unroll
                for (int e = 0; e < 2; e++) {
                    int col = blockCol + wn * 64 + nt * 8 + 2 * qk + e;
                    float v = acc[mt][nt][half * 2 + e];
                    if (bias) v += bias[col];
                    if (act) {
                        float xg = v;
                        v = 0.5f * xg * (1.f + tanhf(0.7978845608028654f *
                                (xg + 0.044715f * xg * xg * xg)));
                    }
                    if (gate) v *= gate[bch * ADAW + col];
                    if (arow) v += arow[col];
                    if (crow) crow[col] = v;
                    if (hrow) hrow[col] = __float2half(v);
                }
            }
        }
    }
}

// ---------------- ada = silu(c4t) @ W_ada + b_ada -------------------------
__global__ __launch_bounds__(128) void ada_kernel(
    const float* __restrict__ c4t, const float* __restrict__ W,
    const float* __restrict__ bias)
{
    __shared__ float ss[MM];
    int b = blockIdx.y;
    for (int i = threadIdx.x; i < MM; i += 128) {
        float v = c4t[b * MM + i];
        ss[i] = v / (1.f + expf(-v));
    }
    __syncthreads();
    int col = blockIdx.x * 128 + threadIdx.x;
    float acc = bias[col];
    for (int k = 0; k < MM; k++)
        acc += ss[k] * W[(size_t)k * ADAW + col];
    g_ada[b * ADAW + col] = acc;
}

// ---------------- rope tables ---------------------------------------------
__global__ void rope_kernel(const int* __restrict__ f)
{
    int idx = threadIdx.x;
    if (idx < TT * (DD / 2)) {
        int t = idx / (DD / 2), i = idx % (DD / 2);
        float pos = (float)f[t];
        float freq = powf(10000.f, -((2.f * (float)i) / (float)DD));
        float a = pos * freq;
        g_ropec[idx] = cosf(a);
        g_ropes[idx] = sinf(a);
    }
}

// ---------------- extra-KV projections (packed f32x2) ----------------------
__global__ __launch_bounds__(256) void ekv_kernel(
    const float* __restrict__ c,
    const float* __restrict__ tk, const float* __restrict__ tv,
    const float* __restrict__ sk, const float* __restrict__ sv)
{
    __shared__ __align__(16) float cs[MM];
    int row = blockIdx.x;
    int which = blockIdx.y;
    const float* W = (which == 0) ? tk : (which == 1) ? tv : (which == 2) ? sk : sv;
    float* O = (which == 0) ? g_tk : (which == 1) ? g_tv : (which == 2) ? g_sk : g_sv;
    for (int i = threadIdx.x; i < MM; i += 256) cs[i] = c[(size_t)row * MM + i];
    __syncthreads();

    int c0 = threadIdx.x;            // col-pair ids: c0, c0+256, (c0+512 if <576)
    unsigned long long a0 = 0ull, a1 = 0ull, a2v = 0ull;
    bool has2 = (c0 + 512) < (MM / 2);
    for (int k = 0; k < MM; k++) {
        unsigned long long csp = packf2(cs[k], cs[k]);
        const float* wr = W + (size_t)k * MM;
        ffma2(a0, csp, *(const unsigned long long*)&wr[2 * c0]);
        ffma2(a1, csp, *(const unsigned long long*)&wr[2 * (c0 + 256)]);
        if (has2) ffma2(a2v, csp, *(const unsigned long long*)&wr[2 * (c0 + 512)]);
    }
    float* orow = O + (size_t)row * MM;
    float2 v0 = unpackf2(a0);
    orow[2 * c0] = v0.x; orow[2 * c0 + 1] = v0.y;
    float2 v1 = unpackf2(a1);
    orow[2 * (c0 + 256)] = v1.x; orow[2 * (c0 + 256) + 1] = v1.y;
    if (has2) {
        float2 v2 = unpackf2(a2v);
        orow[2 * (c0 + 512)] = v2.x; orow[2 * (c0 + 512) + 1] = v2.y;
    }
}

// ---------------- LayerNorm (half output) ----------------------------------
__global__ __launch_bounds__(256) void ln_kernel(
    const float* __restrict__ X, __half* __restrict__ out, float* __restrict__ copyDst,
    const float* __restrict__ w, const float* __restrict__ bvec,
    const float* __restrict__ ada, int shOff, int scOff, float eps, int permute)
{
    int row = blockIdx.x;
    const float* xr = X + (size_t)row * MM;
    float xv[5];
    float s = 0.f, sq = 0.f;
    int k = 0;
    for (int i = threadIdx.x; i < MM; i += 256, k++) {
        float v = xr[i];
        xv[k] = v;
        s += v; sq += v * v;
    }
    __shared__ float reds[8], redq[8], stats[2];
    for (int off = 16; off > 0; off >>= 1) {
        s  += __shfl_xor_sync(0xffffffffu, s,  off);
        sq += __shfl_xor_sync(0xffffffffu, sq, off);
    }
    int wid = threadIdx.x >> 5, lane = threadIdx.x & 31;
    if (lane == 0) { reds[wid] = s; redq[wid] = sq; }
    __syncthreads();
    if (threadIdx.x == 0) {
        float ts = 0.f, tq = 0.f;
        for (int i2 = 0; i2 < 8; i2++) { ts += reds[i2]; tq += redq[i2]; }
        float mean = ts * (1.f / MM);
        float var = tq * (1.f / MM) - mean * mean;
        stats[0] = mean;
        stats[1] = rsqrtf(var + eps);
    }
    __syncthreads();
    float mean = stats[0], rstd = stats[1];
    int b = row >> 12;
    int orow = row;
    if (permute) {
        int rem = row & 4095;
        int t = rem >> 8, n = rem & 255;
        orow = ((b << 8) + n) * TT + t;
    }
    k = 0;
    for (int i = threadIdx.x; i < MM; i += 256, k++) {
        float v = xv[k];
        float nv = (v - mean) * rstd;
        float y;
        if (ada) y = nv * (1.f + ada[b * ADAW + scOff + i]) + ada[b * ADAW + shOff + i];
        else     y = nv * w[i] + bvec[i];
        out[(size_t)orow * MM + i] = __float2half(y);
        if (copyDst) copyDst[(size_t)row * MM + i] = v;
    }
}

// ---------------- temporal attention (packed f32x2 math) -------------------
__global__ __launch_bounds__(256) void attn_t_kernel()
{
    __shared__ __align__(16) float qs[TT * DD];
    __shared__ __align__(16) float kks[2 * TT * DD];
    __shared__ __align__(16) float vvs[2 * TT * DD];
    __shared__ __align__(16) float scs[TT * 2 * TT];
    int h = blockIdx.x, n = blockIdx.y, b = blockIdx.z;
    const __half* base = g_bigh + (size_t)((b * NN + n) * TT) * QKVW + h * DD;

    for (int idx = threadIdx.x; idx < TT * (DD / 2); idx += 256) {
        int t = idx / (DD / 2), i = idx % (DD / 2);
        float cc = g_ropec[idx], ssn = g_ropes[idx];
        const __half* qr = base + (size_t)t * QKVW + 2 * i;
        float x0 = __half2float(qr[0]), x1 = __half2float(qr[1]);
        qs[t * DD + 2 * i]     = SCALE * (x0 * cc - x1 * ssn);
        qs[t * DD + 2 * i + 1] = SCALE * (x1 * cc + x0 * ssn);
        const __half* kr = qr + MM;
        x0 = __half2float(kr[0]); x1 = __half2float(kr[1]);
        kks[(TT + t) * DD + 2 * i]     = x0 * cc - x1 * ssn;
        kks[(TT + t) * DD + 2 * i + 1] = x1 * cc + x0 * ssn;
        const float* er = g_tk + (size_t)(b * TT + t) * MM + h * DD + 2 * i;
        x0 = er[0]; x1 = er[1];
        kks[t * DD + 2 * i]     = x0 * cc - x1 * ssn;
        kks[t * DD + 2 * i + 1] = x1 * cc + x0 * ssn;
    }
    for (int idx = threadIdx.x; idx < TT * DD; idx += 256) {
        int t = idx / DD, d = idx % DD;
        vvs[(TT + t) * DD + d] = __half2float(base[(size_t)t * QKVW + 2 * MM + d]);
        vvs[t * DD + d] = g_tv[(size_t)(b * TT + t) * MM + h * DD + d];
    }
    __syncthreads();

    for (int idx = threadIdx.x; idx < TT * 2 * TT; idx += 256) {
        int t = idx / (2 * TT), j = idx % (2 * TT);
        unsigned long long a2 = 0ull;
#pragma unroll
        for (int dp = 0; dp < DD / 2; dp++)
            ffma2(a2, *(const unsigned long long*)&qs[t * DD + 2 * dp],
                      *(const unsigned long long*)&kks[j * DD + 2 * dp]);
        float2 v = unpackf2(a2);
        scs[idx] = v.x + v.y;
    }
    __syncthreads();

    if (threadIdx.x < TT) {
        int t = threadIdx.x;
        float m = -1e30f;
        for (int j = 0; j < 2 * TT; j++) m = fmaxf(m, scs[t * 2 * TT + j]);
        float sum = 0.f;
        for (int j = 0; j < 2 * TT; j++) {
            float p = __expf(scs[t * 2 * TT + j] - m);
            scs[t * 2 * TT + j] = p;
            sum += p;
        }
        float inv = 1.f / sum;
        for (int j = 0; j < 2 * TT; j++) scs[t * 2 * TT + j] *= inv;
    }
    __syncthreads();

    for (int idx = threadIdx.x; idx < TT * (DD / 2); idx += 256) {
        int t = idx / (DD / 2), dp = idx % (DD / 2);
        unsigned long long a2 = 0ull;
#pragma unroll
        for (int j = 0; j < 2 * TT; j++) {
            unsigned long long p2 = packf2(scs[t * 2 * TT + j], scs[t * 2 * TT + j]);
            ffma2(a2, p2, *(const unsigned long long*)&vvs[j * DD + 2 * dp]);
        }
        float2 v = unpackf2(a2);
        __half2* orow = (__half2*)(g_attnh +
            (size_t)((b * NN + n) * TT + t) * MM + h * DD + 2 * dp);
        *orow = __floats2half2_rn(v.x, v.y);
    }
}

// ---------------- spatial attention: f32x2, 2 threads per query ------------
#define SKV 32
__global__ __launch_bounds__(512) void attn_s_kernel()
{
    __shared__ __align__(16) unsigned long long kt[SKV * 36];
    __shared__ __align__(16) unsigned long long vt[SKV * 36];
    int h = blockIdx.x, t = blockIdx.y, b = blockIdx.z;
    int tid = threadIdx.x;
    int n = tid >> 1, dh = tid & 1;            // pair-split over d-dim
    const __half* base = g_bigh + (size_t)((b * TT + t) * NN) * QKVW;

    unsigned long long qf[18];
    {
        const __half2* qr = (const __half2*)(base + (size_t)n * QKVW + h * DD);
#pragma unroll
        for (int i = 0; i < 18; i++) {
            float2 v = __half22float2(qr[dh * 18 + i]);
            qf[i] = packf2(v.x, v.y);
        }
    }
    unsigned long long acc2[18];
#pragma unroll
    for (int i = 0; i < 18; i++) acc2[i] = 0ull;
    float mcur = -1e30f, lsum = 0.f;

    for (int tile = 0; tile < (NN + 1 + SKV - 1) / SKV; tile++) {
        int j0 = tile * SKV;
        int jcount = (NN + 1) - j0;
        if (jcount > SKV) jcount = SKV;
        __syncthreads();
        for (int idx = tid; idx < jcount * 36; idx += 512) {
            int jj = idx / 36, dp = idx % 36;
            int j = j0 + jj;
            float2 kv, vv;
            if (j == 0) {
                const float* kf = g_sk + (size_t)(b * TT + t) * MM + h * DD + 2 * dp;
                const float* vf = g_sv + (size_t)(b * TT + t) * MM + h * DD + 2 * dp;
                kv = make_float2(kf[0], kf[1]);
                vv = make_float2(vf[0], vf[1]);
            } else {
                kv = __half22float2(*(const __half2*)(base +
                        (size_t)(j - 1) * QKVW + MM + h * DD + 2 * dp));
                vv = __half22float2(*(const __half2*)(base +
                        (size_t)(j - 1) * QKVW + 2 * MM + h * DD + 2 * dp));
            }
            kt[jj * 36 + dp] = packf2(kv.x, kv.y);
            vt[jj * 36 + dp] = packf2(vv.x, vv.y);
        }
        __syncthreads();

        for (int jj = 0; jj < jcount; jj++) {
            unsigned long long s2 = 0ull;
            const unsigned long long* krow = kt + jj * 36 + dh * 18;
#pragma unroll
            for (int i = 0; i < 18; i++) ffma2(s2, qf[i], krow[i]);
            float2 sp = unpackf2(s2);
            float s = sp.x + sp.y;
            s += __shfl_xor_sync(0xffffffffu, s, 1);   // pair merge (commutative)
            s *= SCALE;
            if (s > mcur) {
                float cc = __expf(mcur - s);
                unsigned long long c2 = packf2(cc, cc);
                lsum *= cc;
#pragma unroll
                for (int i = 0; i < 18; i++) fmul2(acc2[i], c2, acc2[i]);
                mcur = s;
            }
            float p = __expf(s - mcur);
            lsum += p;
            unsigned long long p2 = packf2(p, p);
            const unsigned long long* vrow = vt + jj * 36 + dh * 18;
#pragma unroll
            for (int i = 0; i < 18; i++) ffma2(acc2[i], p2, vrow[i]);
        }
    }
    float inv = 1.f / lsum;
    __half2* orow = (__half2*)(g_attnh +
        (size_t)((b * TT + t) * NN + n) * MM + h * DD) + dh * 18;
#pragma unroll
    for (int i = 0; i < 18; i++) {
        float2 v = unpackf2(acc2[i]);
        orow[i] = __floats2half2_rn(v.x * inv, v.y * inv);
    }
}

// ---------------- launch ----------------------------------------------------
extern "C" void kernel_launch(void* const* d_in, const int* in_sizes, int n_in,
                              void* d_out, int out_size)
{
    (void)in_sizes; (void)n_in; (void)out_size;
    const float* x      = (const float*)d_in[0];
    const float* c4t    = (const float*)d_in[1];
    const float* c      = (const float*)d_in[2];
    const float* W_ada  = (const float*)d_in[3];
    const float* b_ada  = (const float*)d_in[4];
    const float* tn_w   = (const float*)d_in[5];
    const float* tn_b   = (const float*)d_in[6];
    const float* t_qkv  = (const float*)d_in[7];
    const float* t_k    = (const float*)d_in[8];
    const float* t_v    = (const float*)d_in[9];
    const float* t_out  = (const float*)d_in[10];
    const float* t_fc_w = (const float*)d_in[11];
    const float* t_fc_b = (const float*)d_in[12];
    const float* s_qkv  = (const float*)d_in[13];
    const float* s_k    = (const float*)d_in[14];
    const float* s_v    = (const float*)d_in[15];
    const float* s_out  = (const float*)d_in[16];
    const float* mlp_w1 = (const float*)d_in[17];
    const float* mlp_b1 = (const float*)d_in[18];
    const float* mlp_w2 = (const float*)d_in[19];
    const float* mlp_b2 = (const float*)d_in[20];
    const int*   f      = (const int*)d_in[21];
    float* out = (float*)d_out;

    float *px4, *pada;
    __half *plnh, *pattnh, *pbigh;
    __half *wtq, *wtoutrm, *wtf, *wcomb, *wsq, *wso, *ww1, *ww2;
    cudaGetSymbolAddress((void**)&px4,    g_x4);
    cudaGetSymbolAddress((void**)&pada,   g_ada);
    cudaGetSymbolAddress((void**)&plnh,   g_lnh);
    cudaGetSymbolAddress((void**)&pattnh, g_attnh);
    cudaGetSymbolAddress((void**)&pbigh,  g_bigh);
    cudaGetSymbolAddress((void**)&wtq,    g_wh_tqkv);
    cudaGetSymbolAddress((void**)&wtoutrm,g_wh_toutrm);
    cudaGetSymbolAddress((void**)&wtf,    g_wh_tfc);
    cudaGetSymbolAddress((void**)&wcomb,  g_wh_comb);
    cudaGetSymbolAddress((void**)&wsq,    g_wh_sqkv);
    cudaGetSymbolAddress((void**)&wso,    g_wh_sout);
    cudaGetSymbolAddress((void**)&ww1,    g_wh_w1);
    cudaGetSymbolAddress((void**)&ww2,    g_wh_w2);

    cudaFuncSetAttribute(tc_gemm_kernel,
                         cudaFuncAttributeMaxDynamicSharedMemorySize, TCG_SMEM);

    // weight convert/transpose
    convw_kernel<<<dim3(QKVW / 32, MM / 32), dim3(32, 8)>>>(t_qkv, wtq, MM, QKVW);
    convh_kernel<<<(MM * MM + 255) / 256, 256>>>(t_out, wtoutrm, MM * MM);
    convw_kernel<<<dim3(MM / 32, MM / 32), dim3(32, 8)>>>(t_fc_w, wtf, MM, MM);
    convw_kernel<<<dim3(QKVW / 32, MM / 32), dim3(32, 8)>>>(s_qkv, wsq, MM, QKVW);
    convw_kernel<<<dim3(MM / 32, MM / 32), dim3(32, 8)>>>(s_out, wso, MM, MM);
    convw_kernel<<<dim3(MLPW / 32, MM / 32), dim3(32, 8)>>>(mlp_w1, ww1, MM, MLPW);
    convw_kernel<<<dim3(MM / 32, MLPW / 32), dim3(32, 8)>>>(mlp_w2, ww2, MLPW, MM);

    // Wc^T[n][k0] = sum_j t_fc^T[n][j] * t_out[k0][j]
    tc_gemm_kernel<<<dim3(MM / 128, MM / 128), 256, TCG_SMEM>>>(
        wtf, wtoutrm, nullptr, nullptr, nullptr, nullptr, wcomb, MM, MM, 0, 0);

    ada_kernel<<<dim3(ADAW / 128, BB), 128>>>(c4t, W_ada, b_ada);
    rope_kernel<<<1, TT * (DD / 2)>>>(f);
    ekv_kernel<<<dim3(BB * TT, 4), 256>>>(c, t_k, t_v, s_k, s_v);

    // temporal branch
    ln_kernel<<<ROWS, 256>>>(x, plnh, px4, tn_w, tn_b, nullptr, 0, 0, 1e-5f, 1);
    tc_gemm_kernel<<<dim3(QKVW / 128, ROWS / 128), 256, TCG_SMEM>>>(
        plnh, wtq, nullptr, nullptr, nullptr, nullptr, pbigh, MM, QKVW, 0, 0);
    attn_t_kernel<<<dim3(HH, NN, BB), 256>>>();
    tc_gemm_kernel<<<dim3(MM / 128, ROWS / 128), 256, TCG_SMEM>>>(
        pattnh, wcomb, t_fc_b, px4, nullptr, px4, nullptr, MM, MM, 0, 1);

    // spatial branch
    ln_kernel<<<ROWS, 256>>>(px4, plnh, nullptr, nullptr, nullptr, pada, 0, MM, 1e-6f, 0);
    tc_gemm_kernel<<<dim3(QKVW / 128, ROWS / 128), 256, TCG_SMEM>>>(
        plnh, wsq, nullptr, nullptr, nullptr, nullptr, pbigh, MM, QKVW, 0, 0);
    attn_s_kernel<<<dim3(HH, TT, BB), 512>>>();
    tc_gemm_kernel<<<dim3(MM / 128, ROWS / 128), 256, TCG_SMEM>>>(
        pattnh, wso, nullptr, px4, pada + 2 * MM, px4, nullptr, MM, MM, 0, 0);

    // MLP
    ln_kernel<<<ROWS, 256>>>(px4, plnh, nullptr, nullptr, nullptr, pada, 3 * MM, 4 * MM, 1e-6f, 0);
    tc_gemm_kernel<<<dim3(MLPW / 128, ROWS / 128), 256, TCG_SMEM>>>(
        plnh, ww1, mlp_b1, nullptr, nullptr, nullptr, pbigh, MM, MLPW, 1, 0);
    tc_gemm_kernel<<<dim3(MM / 128, ROWS / 128), 256, TCG_SMEM>>>(
        pbigh, ww2, mlp_b2, px4, pada + 5 * MM, out, nullptr, MLPW, MM, 0, 0);
}